// round 2
// baseline (speedup 1.0000x reference)
#include <cuda_runtime.h>

#define BATCH 4
#define NB 262144
#define NA 8192
#define FDIM 32
#define HID 64
#define OUT 32

// ---------------- scratch (device globals; no allocation allowed) ----------------
__device__ __align__(16) float g_AP1[BATCH * NA * HID];   // atoms @ e_w1[0:32,:]
__device__ __align__(16) float g_AP2[BATCH * NA * HID];   // atoms @ e_w1[32:64,:]
__device__ __align__(16) float g_accum[BATCH * NA * OUT]; // scatter-sum of bonds_out
__device__ int   g_count[BATCH * NA];
__device__ float g_bsum[BATCH * OUT];  // sum of bonds_out per batch
__device__ float g_asum[BATCH * OUT];  // sum of atoms_out per batch
__device__ float g_hb[BATCH * HID];    // e_b1 + state @ e_w1[96:128,:]

__device__ __forceinline__ float softplus_f(float x) {
    float e = __expf(-fabsf(x));
    return fmaxf(x, 0.0f) + __logf(1.0f + e);
}

// ---------------- zero accumulators ----------------
__global__ void zero_kernel() {
    int t = blockIdx.x * blockDim.x + threadIdx.x;
    int n = gridDim.x * blockDim.x;
    for (int i = t; i < BATCH * NA * OUT; i += n) g_accum[i] = 0.0f;
    for (int i = t; i < BATCH * NA; i += n) g_count[i] = 0;
    if (t < BATCH * OUT) { g_bsum[t] = 0.0f; g_asum[t] = 0.0f; }
}

// ---------------- per-batch layer-1 bias: e_b1 + state @ e_w1[96:128,:] ----------------
__global__ void hb_kernel(const float* __restrict__ state,
                          const float* __restrict__ ew1,
                          const float* __restrict__ eb1) {
    int t = threadIdx.x;            // 256 threads
    int b = t >> 6, j = t & 63;
    float acc = eb1[j];
    for (int i = 0; i < FDIM; ++i)
        acc = fmaf(state[b * FDIM + i], ew1[(96 + i) * HID + j], acc);
    g_hb[b * HID + j] = acc;
}

// ---------------- per-atom precompute of atom contributions to bond layer 1 ----------------
__global__ void ap_kernel(const float* __restrict__ atoms,
                          const float* __restrict__ ew1) {
    extern __shared__ float sm[];
    float* sW = sm;                  // 64*64 (rows 0..63 of e_w1)
    float* scratch = sm + 64 * HID;  // 128*33
    int tid = threadIdx.x;
    for (int i = tid; i < 64 * HID; i += blockDim.x) sW[i] = ew1[i];
    __syncthreads();

    int a = blockIdx.x * blockDim.x + tid;  // global (b*NA + atom)
    float* row = scratch + tid * 33;
    const float4* arow = reinterpret_cast<const float4*>(atoms + (size_t)a * FDIM);
#pragma unroll
    for (int k = 0; k < 8; ++k) {
        float4 v = arow[k];
        row[4 * k + 0] = v.x; row[4 * k + 1] = v.y;
        row[4 * k + 2] = v.z; row[4 * k + 3] = v.w;
    }
    float acc[HID];
#pragma unroll
    for (int j = 0; j < HID; ++j) acc[j] = 0.0f;
    for (int i = 0; i < 32; ++i) {
        float xv = row[i];
        const float4* w = reinterpret_cast<const float4*>(sW + i * HID);
#pragma unroll
        for (int j4 = 0; j4 < 16; ++j4) {
            float4 wv = w[j4];
            acc[4 * j4 + 0] = fmaf(xv, wv.x, acc[4 * j4 + 0]);
            acc[4 * j4 + 1] = fmaf(xv, wv.y, acc[4 * j4 + 1]);
            acc[4 * j4 + 2] = fmaf(xv, wv.z, acc[4 * j4 + 2]);
            acc[4 * j4 + 3] = fmaf(xv, wv.w, acc[4 * j4 + 3]);
        }
    }
    float4* out1 = reinterpret_cast<float4*>(g_AP1 + (size_t)a * HID);
#pragma unroll
    for (int j4 = 0; j4 < 16; ++j4)
        out1[j4] = make_float4(acc[4 * j4], acc[4 * j4 + 1], acc[4 * j4 + 2], acc[4 * j4 + 3]);

#pragma unroll
    for (int j = 0; j < HID; ++j) acc[j] = 0.0f;
    for (int i = 32; i < 64; ++i) {
        float xv = row[i - 32];
        const float4* w = reinterpret_cast<const float4*>(sW + i * HID);
#pragma unroll
        for (int j4 = 0; j4 < 16; ++j4) {
            float4 wv = w[j4];
            acc[4 * j4 + 0] = fmaf(xv, wv.x, acc[4 * j4 + 0]);
            acc[4 * j4 + 1] = fmaf(xv, wv.y, acc[4 * j4 + 1]);
            acc[4 * j4 + 2] = fmaf(xv, wv.z, acc[4 * j4 + 2]);
            acc[4 * j4 + 3] = fmaf(xv, wv.w, acc[4 * j4 + 3]);
        }
    }
    float4* out2 = reinterpret_cast<float4*>(g_AP2 + (size_t)a * HID);
#pragma unroll
    for (int j4 = 0; j4 < 16; ++j4)
        out2[j4] = make_float4(acc[4 * j4], acc[4 * j4 + 1], acc[4 * j4 + 2], acc[4 * j4 + 3]);
}

// ---------------- bond MLP (dominant kernel) ----------------
__global__ void bond_kernel(const float* __restrict__ bonds,
                            const int* __restrict__ ia1,
                            const int* __restrict__ ia2,
                            const float* __restrict__ ew1,
                            const float* __restrict__ eb2,
                            const float* __restrict__ ew2,
                            const float* __restrict__ ew3,
                            const float* __restrict__ eb3,
                            float* __restrict__ out) {
    extern __shared__ float sm[];
    float* sW1b = sm;                      // 32*64  (rows 64..95 of e_w1)
    float* sW2 = sW1b + 32 * HID;          // 64*64
    float* sW3 = sW2 + HID * HID;          // 64*32
    float* scratch = sW3 + HID * OUT;      // 256*65
    float* sHb = scratch + 256 * 65;       // 64
    float* sB2 = sHb + HID;                // 64
    float* sB3 = sB2 + HID;                // 32
    float* sMsum = sB3 + OUT;              // 32

    int tid = threadIdx.x;
    int g = blockIdx.x * 256 + tid;
    int b = g >> 18;   // NB = 2^18; blocks never straddle batches

    for (int i = tid; i < 32 * HID; i += 256) sW1b[i] = ew1[64 * HID + i];
    for (int i = tid; i < HID * HID; i += 256) sW2[i] = ew2[i];
    for (int i = tid; i < HID * OUT; i += 256) sW3[i] = ew3[i];
    if (tid < HID) { sHb[tid] = g_hb[b * HID + tid]; sB2[tid] = eb2[tid]; }
    if (tid < OUT) { sB3[tid] = eb3[tid]; sMsum[tid] = 0.0f; }
    __syncthreads();

    int a1 = ia1[g], a2 = ia2[g];
    float* row = scratch + tid * 65;

    const float4* brow = reinterpret_cast<const float4*>(bonds + (size_t)g * FDIM);
#pragma unroll
    for (int k = 0; k < 8; ++k) {
        float4 v = brow[k];
        row[4 * k + 0] = v.x; row[4 * k + 1] = v.y;
        row[4 * k + 2] = v.z; row[4 * k + 3] = v.w;
    }

    // layer 1: gathered atom tables + state bias + bond part
    float h[HID];
    const float4* p1 = reinterpret_cast<const float4*>(g_AP1 + (size_t)(b * NA + a1) * HID);
    const float4* p2 = reinterpret_cast<const float4*>(g_AP2 + (size_t)(b * NA + a2) * HID);
    const float4* ph = reinterpret_cast<const float4*>(sHb);
#pragma unroll
    for (int j4 = 0; j4 < 16; ++j4) {
        float4 u = p1[j4], v = p2[j4], w = ph[j4];
        h[4 * j4 + 0] = u.x + v.x + w.x;
        h[4 * j4 + 1] = u.y + v.y + w.y;
        h[4 * j4 + 2] = u.z + v.z + w.z;
        h[4 * j4 + 3] = u.w + v.w + w.w;
    }
    for (int i = 0; i < FDIM; ++i) {
        float xv = row[i];
        const float4* wr = reinterpret_cast<const float4*>(sW1b + i * HID);
#pragma unroll
        for (int j4 = 0; j4 < 16; ++j4) {
            float4 wv = wr[j4];
            h[4 * j4 + 0] = fmaf(xv, wv.x, h[4 * j4 + 0]);
            h[4 * j4 + 1] = fmaf(xv, wv.y, h[4 * j4 + 1]);
            h[4 * j4 + 2] = fmaf(xv, wv.z, h[4 * j4 + 2]);
            h[4 * j4 + 3] = fmaf(xv, wv.w, h[4 * j4 + 3]);
        }
    }
#pragma unroll
    for (int j = 0; j < HID; ++j) row[j] = softplus_f(h[j]);

    // layer 2
    float h2[HID];
#pragma unroll
    for (int j = 0; j < HID; ++j) h2[j] = sB2[j];
    for (int i = 0; i < HID; ++i) {
        float xv = row[i];
        const float4* wr = reinterpret_cast<const float4*>(sW2 + i * HID);
#pragma unroll
        for (int j4 = 0; j4 < 16; ++j4) {
            float4 wv = wr[j4];
            h2[4 * j4 + 0] = fmaf(xv, wv.x, h2[4 * j4 + 0]);
            h2[4 * j4 + 1] = fmaf(xv, wv.y, h2[4 * j4 + 1]);
            h2[4 * j4 + 2] = fmaf(xv, wv.z, h2[4 * j4 + 2]);
            h2[4 * j4 + 3] = fmaf(xv, wv.w, h2[4 * j4 + 3]);
        }
    }
#pragma unroll
    for (int j = 0; j < HID; ++j) row[j] = softplus_f(h2[j]);

    // layer 3
    float h3[OUT];
#pragma unroll
    for (int j = 0; j < OUT; ++j) h3[j] = sB3[j];
    for (int i = 0; i < HID; ++i) {
        float xv = row[i];
        const float4* wr = reinterpret_cast<const float4*>(sW3 + i * OUT);
#pragma unroll
        for (int j4 = 0; j4 < 8; ++j4) {
            float4 wv = wr[j4];
            h3[4 * j4 + 0] = fmaf(xv, wv.x, h3[4 * j4 + 0]);
            h3[4 * j4 + 1] = fmaf(xv, wv.y, h3[4 * j4 + 1]);
            h3[4 * j4 + 2] = fmaf(xv, wv.z, h3[4 * j4 + 2]);
            h3[4 * j4 + 3] = fmaf(xv, wv.w, h3[4 * j4 + 3]);
        }
    }
    float o[OUT];
#pragma unroll
    for (int j = 0; j < OUT; ++j) o[j] = softplus_f(h3[j]);

    float4* orow = reinterpret_cast<float4*>(out + (size_t)g * OUT);
#pragma unroll
    for (int j4 = 0; j4 < 8; ++j4)
        orow[j4] = make_float4(o[4 * j4], o[4 * j4 + 1], o[4 * j4 + 2], o[4 * j4 + 3]);

    // scatter-sum into atoms (by bond_atom_1) + count
    float* accp = g_accum + (size_t)(b * NA + a1) * OUT;
#pragma unroll
    for (int j = 0; j < OUT; ++j) atomicAdd(accp + j, o[j]);
    atomicAdd(&g_count[b * NA + a1], 1);

    // per-batch mean partial: warp shuffle reduce -> smem -> global
    int lane = tid & 31;
#pragma unroll
    for (int j = 0; j < OUT; ++j) {
        float v = o[j];
        v += __shfl_xor_sync(0xffffffffu, v, 16);
        v += __shfl_xor_sync(0xffffffffu, v, 8);
        v += __shfl_xor_sync(0xffffffffu, v, 4);
        v += __shfl_xor_sync(0xffffffffu, v, 2);
        v += __shfl_xor_sync(0xffffffffu, v, 1);
        if (lane == 0) atomicAdd(&sMsum[j], v);
    }
    __syncthreads();
    if (tid < OUT) atomicAdd(&g_bsum[b * OUT + tid], sMsum[tid]);
}

// ---------------- atom MLP ----------------
__global__ void atom_kernel(const float* __restrict__ atoms,
                            const float* __restrict__ state,
                            const float* __restrict__ vw1,
                            const float* __restrict__ vb1,
                            const float* __restrict__ vw2,
                            const float* __restrict__ vb2,
                            const float* __restrict__ vw3,
                            const float* __restrict__ vb3,
                            float* __restrict__ out) {
    extern __shared__ float sm[];
    float* sW1 = sm;                    // 96*64
    float* sW2 = sW1 + 96 * HID;        // 64*64
    float* sW3 = sW2 + HID * HID;       // 64*32
    float* scratch = sW3 + HID * OUT;   // 128*97
    float* sB1 = scratch + 128 * 97;    // 64
    float* sB2 = sB1 + HID;             // 64
    float* sB3 = sB2 + HID;             // 32
    float* sMsum = sB3 + OUT;           // 32

    int tid = threadIdx.x;
    int a = blockIdx.x * 128 + tid;     // global (b*NA + atom)
    int b = a >> 13;                    // NA = 2^13

    for (int i = tid; i < 96 * HID; i += 128) sW1[i] = vw1[i];
    for (int i = tid; i < HID * HID; i += 128) sW2[i] = vw2[i];
    for (int i = tid; i < HID * OUT; i += 128) sW3[i] = vw3[i];
    if (tid < HID) { sB1[tid] = vb1[tid]; sB2[tid] = vb2[tid]; }
    if (tid < OUT) { sB3[tid] = vb3[tid]; sMsum[tid] = 0.0f; }
    __syncthreads();

    float* row = scratch + tid * 97;

    float inv = 1.0f / (float)g_count[a];
    const float4* pa = reinterpret_cast<const float4*>(g_accum + (size_t)a * OUT);
#pragma unroll
    for (int k = 0; k < 8; ++k) {
        float4 v = pa[k];
        row[4 * k + 0] = v.x * inv; row[4 * k + 1] = v.y * inv;
        row[4 * k + 2] = v.z * inv; row[4 * k + 3] = v.w * inv;
    }
    const float4* pt = reinterpret_cast<const float4*>(atoms + (size_t)a * FDIM);
#pragma unroll
    for (int k = 0; k < 8; ++k) {
        float4 v = pt[k];
        row[32 + 4 * k + 0] = v.x; row[32 + 4 * k + 1] = v.y;
        row[32 + 4 * k + 2] = v.z; row[32 + 4 * k + 3] = v.w;
    }
    const float4* ps = reinterpret_cast<const float4*>(state + (size_t)b * FDIM);
#pragma unroll
    for (int k = 0; k < 8; ++k) {
        float4 v = ps[k];
        row[64 + 4 * k + 0] = v.x; row[64 + 4 * k + 1] = v.y;
        row[64 + 4 * k + 2] = v.z; row[64 + 4 * k + 3] = v.w;
    }

    // layer 1 (96 -> 64)
    float h[HID];
#pragma unroll
    for (int j = 0; j < HID; ++j) h[j] = sB1[j];
    for (int i = 0; i < 96; ++i) {
        float xv = row[i];
        const float4* wr = reinterpret_cast<const float4*>(sW1 + i * HID);
#pragma unroll
        for (int j4 = 0; j4 < 16; ++j4) {
            float4 wv = wr[j4];
            h[4 * j4 + 0] = fmaf(xv, wv.x, h[4 * j4 + 0]);
            h[4 * j4 + 1] = fmaf(xv, wv.y, h[4 * j4 + 1]);
            h[4 * j4 + 2] = fmaf(xv, wv.z, h[4 * j4 + 2]);
            h[4 * j4 + 3] = fmaf(xv, wv.w, h[4 * j4 + 3]);
        }
    }
#pragma unroll
    for (int j = 0; j < HID; ++j) row[j] = softplus_f(h[j]);

    // layer 2
    float h2[HID];
#pragma unroll
    for (int j = 0; j < HID; ++j) h2[j] = sB2[j];
    for (int i = 0; i < HID; ++i) {
        float xv = row[i];
        const float4* wr = reinterpret_cast<const float4*>(sW2 + i * HID);
#pragma unroll
        for (int j4 = 0; j4 < 16; ++j4) {
            float4 wv = wr[j4];
            h2[4 * j4 + 0] = fmaf(xv, wv.x, h2[4 * j4 + 0]);
            h2[4 * j4 + 1] = fmaf(xv, wv.y, h2[4 * j4 + 1]);
            h2[4 * j4 + 2] = fmaf(xv, wv.z, h2[4 * j4 + 2]);
            h2[4 * j4 + 3] = fmaf(xv, wv.w, h2[4 * j4 + 3]);
        }
    }
#pragma unroll
    for (int j = 0; j < HID; ++j) row[j] = softplus_f(h2[j]);

    // layer 3
    float h3[OUT];
#pragma unroll
    for (int j = 0; j < OUT; ++j) h3[j] = sB3[j];
    for (int i = 0; i < HID; ++i) {
        float xv = row[i];
        const float4* wr = reinterpret_cast<const float4*>(sW3 + i * OUT);
#pragma unroll
        for (int j4 = 0; j4 < 8; ++j4) {
            float4 wv = wr[j4];
            h3[4 * j4 + 0] = fmaf(xv, wv.x, h3[4 * j4 + 0]);
            h3[4 * j4 + 1] = fmaf(xv, wv.y, h3[4 * j4 + 1]);
            h3[4 * j4 + 2] = fmaf(xv, wv.z, h3[4 * j4 + 2]);
            h3[4 * j4 + 3] = fmaf(xv, wv.w, h3[4 * j4 + 3]);
        }
    }
    float o[OUT];
#pragma unroll
    for (int j = 0; j < OUT; ++j) o[j] = softplus_f(h3[j]);

    float4* orow = reinterpret_cast<float4*>(out + (size_t)(BATCH * NB * OUT) + (size_t)a * OUT);
#pragma unroll
    for (int j4 = 0; j4 < 8; ++j4)
        orow[j4] = make_float4(o[4 * j4], o[4 * j4 + 1], o[4 * j4 + 2], o[4 * j4 + 3]);

    int lane = tid & 31;
#pragma unroll
    for (int j = 0; j < OUT; ++j) {
        float v = o[j];
        v += __shfl_xor_sync(0xffffffffu, v, 16);
        v += __shfl_xor_sync(0xffffffffu, v, 8);
        v += __shfl_xor_sync(0xffffffffu, v, 4);
        v += __shfl_xor_sync(0xffffffffu, v, 2);
        v += __shfl_xor_sync(0xffffffffu, v, 1);
        if (lane == 0) atomicAdd(&sMsum[j], v);
    }
    __syncthreads();
    if (tid < OUT) atomicAdd(&g_asum[b * OUT + tid], sMsum[tid]);
}

// ---------------- state MLP ----------------
__global__ void state_kernel(const float* __restrict__ state,
                             const float* __restrict__ uw1,
                             const float* __restrict__ ub1,
                             const float* __restrict__ uw2,
                             const float* __restrict__ ub2,
                             const float* __restrict__ uw3,
                             const float* __restrict__ ub3,
                             float* __restrict__ out) {
    __shared__ float uin[96];
    __shared__ float h1s[HID];
    __shared__ float h2s[HID];
    int b = blockIdx.x;
    int j = threadIdx.x;   // 64 threads
    if (j < 32) {
        uin[j] = g_bsum[b * OUT + j] * (1.0f / (float)NB);
        uin[32 + j] = g_asum[b * OUT + j] * (1.0f / (float)NA);
        uin[64 + j] = state[b * FDIM + j];
    }
    __syncthreads();
    float acc = ub1[j];
    for (int i = 0; i < 96; ++i) acc = fmaf(uin[i], uw1[i * HID + j], acc);
    h1s[j] = softplus_f(acc);
    __syncthreads();
    acc = ub2[j];
    for (int i = 0; i < HID; ++i) acc = fmaf(h1s[i], uw2[i * HID + j], acc);
    h2s[j] = softplus_f(acc);
    __syncthreads();
    if (j < OUT) {
        acc = ub3[j];
        for (int i = 0; i < HID; ++i) acc = fmaf(h2s[i], uw3[i * OUT + j], acc);
        out[(size_t)(BATCH * NB * OUT) + (size_t)(BATCH * NA * OUT) + b * OUT + j] = softplus_f(acc);
    }
}

// ---------------- launch ----------------
extern "C" void kernel_launch(void* const* d_in, const int* in_sizes, int n_in,
                              void* d_out, int out_size) {
    const float* bonds = (const float*)d_in[0];
    const int* ia1 = (const int*)d_in[1];
    const int* ia2 = (const int*)d_in[2];
    const float* atoms = (const float*)d_in[3];
    const float* state = (const float*)d_in[4];
    const float* ew1 = (const float*)d_in[5];
    const float* eb1 = (const float*)d_in[6];
    const float* ew2 = (const float*)d_in[7];
    const float* eb2 = (const float*)d_in[8];
    const float* ew3 = (const float*)d_in[9];
    const float* eb3 = (const float*)d_in[10];
    const float* vw1 = (const float*)d_in[11];
    const float* vb1 = (const float*)d_in[12];
    const float* vw2 = (const float*)d_in[13];
    const float* vb2 = (const float*)d_in[14];
    const float* vw3 = (const float*)d_in[15];
    const float* vb3 = (const float*)d_in[16];
    const float* uw1 = (const float*)d_in[17];
    const float* ub1 = (const float*)d_in[18];
    const float* uw2 = (const float*)d_in[19];
    const float* ub2 = (const float*)d_in[20];
    const float* uw3 = (const float*)d_in[21];
    const float* ub3 = (const float*)d_in[22];
    float* out = (float*)d_out;

    const int AP_SMEM   = (64 * HID + 128 * 33) * (int)sizeof(float);
    const int BOND_SMEM = (32 * HID + HID * HID + HID * OUT + 256 * 65 + HID + HID + OUT + OUT) * (int)sizeof(float);
    const int ATOM_SMEM = (96 * HID + HID * HID + HID * OUT + 128 * 97 + HID + HID + OUT + OUT) * (int)sizeof(float);

    cudaFuncSetAttribute(ap_kernel, cudaFuncAttributeMaxDynamicSharedMemorySize, AP_SMEM);
    cudaFuncSetAttribute(bond_kernel, cudaFuncAttributeMaxDynamicSharedMemorySize, BOND_SMEM);
    cudaFuncSetAttribute(atom_kernel, cudaFuncAttributeMaxDynamicSharedMemorySize, ATOM_SMEM);

    zero_kernel<<<1024, 256>>>();
    hb_kernel<<<1, 256>>>(state, ew1, eb1);
    ap_kernel<<<(BATCH * NA) / 128, 128, AP_SMEM>>>(atoms, ew1);
    bond_kernel<<<(BATCH * NB) / 256, 256, BOND_SMEM>>>(bonds, ia1, ia2, ew1, eb2, ew2, ew3, eb3, out);
    atom_kernel<<<(BATCH * NA) / 128, 128, ATOM_SMEM>>>(atoms, state, vw1, vb1, vw2, vb2, vw3, vb3, out);
    state_kernel<<<BATCH, 64>>>(state, uw1, ub1, uw2, ub2, uw3, ub3, out);
}